// round 3
// baseline (speedup 1.0000x reference)
#include <cuda_runtime.h>
#include <cuda_bf16.h>
#include <cstdint>

#define DINLINE __device__ __forceinline__

constexpr int DIM = 4096;   // K
constexpr int SEQ = 4096;   // M
constexpr int OUT = 4096;   // N

// ---------------------------------------------------------------------------
// Device scratch (allocation-free rule: __device__ globals)
// ---------------------------------------------------------------------------
__device__ int8_t g_qx[(size_t)SEQ * DIM];   // quantized activations (int8)
__device__ int8_t g_wb[(size_t)OUT * DIM];   // ternary weights (int8)
__device__ float  g_rscale[SEQ];             // 1/scale per token

// ---------------------------------------------------------------------------
// PTX helpers (sm_100 baseline ISA only: cp.async, ldmatrix, mma.sync)
// ---------------------------------------------------------------------------
DINLINE uint32_t smem_u32(const void* p) {
    uint32_t a;
    asm("{ .reg .u64 t; cvta.to.shared.u64 t, %1; cvt.u32.u64 %0, t; }" : "=r"(a) : "l"(p));
    return a;
}

#define CP_ASYNC16(dst, src) \
    asm volatile("cp.async.cg.shared.global [%0], [%1], 16;" :: "r"(dst), "l"(src))
#define CP_COMMIT() asm volatile("cp.async.commit_group;" ::: "memory")
#define CP_WAIT2()  asm volatile("cp.async.wait_group 2;" ::: "memory")
#define CP_WAIT0()  asm volatile("cp.async.wait_group 0;" ::: "memory")

DINLINE void ldm_x4(uint32_t* r, uint32_t addr) {
    asm volatile("ldmatrix.sync.aligned.m8n8.x4.shared.b16 {%0,%1,%2,%3}, [%4];"
                 : "=r"(r[0]), "=r"(r[1]), "=r"(r[2]), "=r"(r[3]) : "r"(addr));
}

DINLINE void mma_s8(int* c, const uint32_t* a, const uint32_t* b) {
    asm volatile(
        "mma.sync.aligned.m16n8k32.row.col.s32.s8.s8.s32 "
        "{%0,%1,%2,%3}, {%4,%5,%6,%7}, {%8,%9}, {%0,%1,%2,%3};"
        : "+r"(c[0]), "+r"(c[1]), "+r"(c[2]), "+r"(c[3])
        : "r"(a[0]), "r"(a[1]), "r"(a[2]), "r"(a[3]), "r"(b[0]), "r"(b[1]));
}

// ---------------------------------------------------------------------------
// Kernel 1: per-row BitNet activation quant  x[f32] -> g_qx[int8], g_rscale
// ---------------------------------------------------------------------------
DINLINE int q1(float v, float s) {
    return (int)fminf(fmaxf(rintf(v * s), -128.f), 127.f);
}
DINLINE uint32_t qpack4(float4 v, float s) {
    uint32_t b0 = (uint32_t)q1(v.x, s) & 0xFF;
    uint32_t b1 = (uint32_t)q1(v.y, s) & 0xFF;
    uint32_t b2 = (uint32_t)q1(v.z, s) & 0xFF;
    uint32_t b3 = (uint32_t)q1(v.w, s) & 0xFF;
    return b0 | (b1 << 8) | (b2 << 16) | (b3 << 24);
}

__global__ void __launch_bounds__(256) quant_kernel(const float* __restrict__ x) {
    const int row = blockIdx.x;
    const int tid = threadIdx.x;
    const float4* xr = reinterpret_cast<const float4*>(x + (size_t)row * DIM);

    float4 v[4];
    float m = 0.f;
#pragma unroll
    for (int i = 0; i < 4; i++) {
        v[i] = xr[tid + i * 256];
        m = fmaxf(m, fmaxf(fmaxf(fabsf(v[i].x), fabsf(v[i].y)),
                           fmaxf(fabsf(v[i].z), fabsf(v[i].w))));
    }
    __shared__ float red[8];
#pragma unroll
    for (int o = 16; o > 0; o >>= 1) m = fmaxf(m, __shfl_xor_sync(~0u, m, o));
    if ((tid & 31) == 0) red[tid >> 5] = m;
    __syncthreads();
    if (tid < 8) {
        float t = red[tid];
#pragma unroll
        for (int o = 4; o > 0; o >>= 1) t = fmaxf(t, __shfl_xor_sync(0xff, t, o));
        if (tid == 0) {
            float scale = 127.0f / fmaxf(t, 1e-5f);
            red[0] = scale;
            g_rscale[row] = 1.0f / scale;
        }
    }
    __syncthreads();
    const float scale = red[0];

    uint32_t* qr = reinterpret_cast<uint32_t*>(g_qx + (size_t)row * DIM);
#pragma unroll
    for (int i = 0; i < 4; i++) qr[tid + i * 256] = qpack4(v[i], scale);
}

// ---------------------------------------------------------------------------
// Kernel 2: W f32 -> int8 (ternary, exact)
// ---------------------------------------------------------------------------
__global__ void __launch_bounds__(256) wconv_kernel(const float* __restrict__ W) {
    const int tid = threadIdx.x;
    const float4* src = reinterpret_cast<const float4*>(W);
    uint32_t* dst = reinterpret_cast<uint32_t*>(g_wb);
#pragma unroll
    for (int i = 0; i < 4; i++) {
        size_t idx = (size_t)blockIdx.x * 1024 + tid + i * 256;
        float4 v = src[idx];
        uint32_t b0 = (uint32_t)(int)v.x & 0xFF;
        uint32_t b1 = (uint32_t)(int)v.y & 0xFF;
        uint32_t b2 = (uint32_t)(int)v.z & 0xFF;
        uint32_t b3 = (uint32_t)(int)v.w & 0xFF;
        dst[idx] = b0 | (b1 << 8) | (b2 << 16) | (b3 << 24);
    }
}

// ---------------------------------------------------------------------------
// Kernel 3: int8 IMMA GEMM  out[m,n] = (sum_k q*W) * rscale[m] + bias[n], * 1/ws
// CTA tile 128x128, K-stage 64B, 4-stage cp.async, 8 warps (warp tile 32x64)
// ---------------------------------------------------------------------------
constexpr int MT = 128;
constexpr int NT = 128;
constexpr int KSTG = 64;                      // int8 elems (= bytes) per K stage
constexpr int STAGES = 4;
constexpr int NKIT = DIM / KSTG;              // 64
constexpr int ASTRIDE = 80;                   // padded row stride (conflict-free ldmatrix)
constexpr uint32_t TILE_BYTES = 128 * ASTRIDE;        // 10240 per operand
constexpr uint32_t STAGE_BYTES = 2 * TILE_BYTES;      // 20480
constexpr uint32_t SM_TOTAL = STAGES * STAGE_BYTES;   // 81920

__global__ void __launch_bounds__(256, 2) gemm_kernel(const float* __restrict__ bias,
                                                      const float* __restrict__ wsp,
                                                      float* __restrict__ out) {
    extern __shared__ char smem[];
    const uint32_t sb = smem_u32(smem);
    const int tid = threadIdx.x;
    const int lane = tid & 31;
    const int warp = tid >> 5;
    const int warp_m = warp & 3;      // 4 warps along M  (4*32 = 128)
    const int warp_n = warp >> 2;     // 2 warps along N  (2*64 = 128)
    const int m0 = blockIdx.y * MT;
    const int n0 = blockIdx.x * NT;

    const char* const abase = reinterpret_cast<const char*>(g_qx) + (size_t)m0 * DIM;
    const char* const bbase = reinterpret_cast<const char*>(g_wb) + (size_t)n0 * DIM;

    // cp.async layout for this thread: 2 A chunks + 2 B chunks of 16B per stage
    // chunk c in [0,512): row = c>>2, seg = c&3
    auto load_stage = [&](int kit) {
        const uint32_t sbb = sb + (uint32_t)(kit % STAGES) * STAGE_BYTES;
        const size_t kbyte = (size_t)kit * KSTG;
#pragma unroll
        for (int i = 0; i < 2; i++) {
            int c = tid + i * 256;
            int row = c >> 2, seg = c & 3;
            CP_ASYNC16(sbb + row * ASTRIDE + seg * 16,
                       abase + (size_t)row * DIM + kbyte + seg * 16);
        }
#pragma unroll
        for (int i = 0; i < 2; i++) {
            int c = tid + i * 256;
            int row = c >> 2, seg = c & 3;
            CP_ASYNC16(sbb + TILE_BYTES + row * ASTRIDE + seg * 16,
                       bbase + (size_t)row * DIM + kbyte + seg * 16);
        }
    };

    // ldmatrix lane addressing (stage-0 relative)
    // A x4 tile (m16 x k32): matrices [r0-7,k0-15][r8-15,k0-15][r0-7,k16-31][r8-15,k16-31]
    const int aRow = (lane & 7) + ((lane >> 3) & 1) * 8;
    const int aKoff = (lane >> 4) * 16;
    const uint32_t addrA0 = sb + (uint32_t)((warp_m * 32 + aRow) * ASTRIDE + aKoff);
    // B x4 group j covers n-tiles 2j,2j+1:
    // matrices [n0-7,k0-15][n0-7,k16-31][n8-15,k0-15][n8-15,k16-31]
    const int bRow = (lane & 7) + (lane >> 4) * 8;
    const int bKoff = ((lane >> 3) & 1) * 16;
    uint32_t addrB0[4];
#pragma unroll
    for (int j = 0; j < 4; j++)
        addrB0[j] = sb + TILE_BYTES +
                    (uint32_t)((warp_n * 64 + j * 16 + bRow) * ASTRIDE + bKoff);

    int acc[2][8][4];
#pragma unroll
    for (int tm = 0; tm < 2; tm++)
#pragma unroll
        for (int tn = 0; tn < 8; tn++)
#pragma unroll
            for (int r = 0; r < 4; r++) acc[tm][tn][r] = 0;

    // prologue: fill 3 stages
    load_stage(0); CP_COMMIT();
    load_stage(1); CP_COMMIT();
    load_stage(2); CP_COMMIT();

    for (int i = 0; i < NKIT; i++) {
        CP_WAIT2();
        __syncthreads();

        // issue loads for stage i+3 first (overlap with compute)
        if (i + 3 < NKIT) load_stage(i + 3);
        CP_COMMIT();

        const uint32_t so = (uint32_t)(i % STAGES) * STAGE_BYTES;
#pragma unroll
        for (int ks = 0; ks < 2; ks++) {
            const uint32_t ko = so + ks * 32;
            uint32_t af[2][4];
            ldm_x4(af[0], addrA0 + ko);
            ldm_x4(af[1], addrA0 + ko + 16 * ASTRIDE);
            uint32_t bf[8][2];
#pragma unroll
            for (int j = 0; j < 4; j++) {
                uint32_t r[4];
                ldm_x4(r, addrB0[j] + ko);
                bf[2 * j][0] = r[0]; bf[2 * j][1] = r[1];
                bf[2 * j + 1][0] = r[2]; bf[2 * j + 1][1] = r[3];
            }
#pragma unroll
            for (int tm = 0; tm < 2; tm++)
#pragma unroll
                for (int tn = 0; tn < 8; tn++)
                    mma_s8(acc[tm][tn], af[tm], bf[tn]);
        }
        __syncthreads();
    }
    CP_WAIT0();

    // -------------------- epilogue --------------------
    const float inv_ws = 1.0f / wsp[0];
#pragma unroll
    for (int tm = 0; tm < 2; tm++) {
        const int r0 = m0 + warp_m * 32 + tm * 16 + (lane >> 2);
        const int r1 = r0 + 8;
        const float rs0 = g_rscale[r0];
        const float rs1 = g_rscale[r1];
        float* o0 = out + (size_t)r0 * OUT;
        float* o1 = out + (size_t)r1 * OUT;
#pragma unroll
        for (int tn = 0; tn < 8; tn++) {
            const int col = n0 + warp_n * 64 + tn * 8 + (lane & 3) * 2;
            const float b0v = bias[col], b1v = bias[col + 1];
            float2 v0, v1;
            v0.x = ((float)acc[tm][tn][0] * rs0 + b0v) * inv_ws;
            v0.y = ((float)acc[tm][tn][1] * rs0 + b1v) * inv_ws;
            v1.x = ((float)acc[tm][tn][2] * rs1 + b0v) * inv_ws;
            v1.y = ((float)acc[tm][tn][3] * rs1 + b1v) * inv_ws;
            *reinterpret_cast<float2*>(o0 + col) = v0;
            *reinterpret_cast<float2*>(o1 + col) = v1;
        }
    }
}

// ---------------------------------------------------------------------------
// Launch
// ---------------------------------------------------------------------------
extern "C" void kernel_launch(void* const* d_in, const int* in_sizes, int n_in,
                              void* d_out, int out_size) {
    (void)in_sizes; (void)n_in; (void)out_size;
    const float* x    = (const float*)d_in[0];
    const float* W    = (const float*)d_in[1];
    const float* bias = (const float*)d_in[2];
    const float* ws   = (const float*)d_in[3];
    float* out = (float*)d_out;

    quant_kernel<<<SEQ, 256>>>(x);
    wconv_kernel<<<(int)(((size_t)OUT * DIM / 4) / 1024), 256>>>(W);

    cudaFuncSetAttribute(gemm_kernel, cudaFuncAttributeMaxDynamicSharedMemorySize, SM_TOTAL);
    gemm_kernel<<<dim3(OUT / NT, SEQ / MT), 256, SM_TOTAL>>>(bias, ws, out);
}

// round 4
// speedup vs baseline: 1.1415x; 1.1415x over previous
#include <cuda_runtime.h>
#include <cuda_bf16.h>
#include <cstdint>

#define DINLINE __device__ __forceinline__

constexpr int DIM = 4096;   // K
constexpr int SEQ = 4096;   // M
constexpr int OUT = 4096;   // N

// ---------------------------------------------------------------------------
// Device scratch (allocation-free rule: __device__ globals)
// ---------------------------------------------------------------------------
__device__ int8_t g_qx[(size_t)SEQ * DIM];   // quantized activations (int8)
__device__ int8_t g_wb[(size_t)OUT * DIM];   // ternary weights (int8)
__device__ float  g_rscale[SEQ];             // 1/scale per token

// ---------------------------------------------------------------------------
// PTX helpers (sm_100 baseline ISA: cp.async, ldmatrix, mma.sync)
// ---------------------------------------------------------------------------
DINLINE uint32_t smem_u32(const void* p) {
    uint32_t a;
    asm("{ .reg .u64 t; cvta.to.shared.u64 t, %1; cvt.u32.u64 %0, t; }" : "=r"(a) : "l"(p));
    return a;
}

#define CP_ASYNC16(dst, src) \
    asm volatile("cp.async.cg.shared.global [%0], [%1], 16;" :: "r"(dst), "l"(src))
#define CP_COMMIT() asm volatile("cp.async.commit_group;" ::: "memory")
#define CP_WAIT2()  asm volatile("cp.async.wait_group 2;" ::: "memory")

DINLINE void ldm_x4(uint32_t* r, uint32_t addr) {
    asm volatile("ldmatrix.sync.aligned.m8n8.x4.shared.b16 {%0,%1,%2,%3}, [%4];"
                 : "=r"(r[0]), "=r"(r[1]), "=r"(r[2]), "=r"(r[3]) : "r"(addr));
}

DINLINE void mma_s8(int* c, const uint32_t* a, const uint32_t* b) {
    asm volatile(
        "mma.sync.aligned.m16n8k32.row.col.s32.s8.s8.s32 "
        "{%0,%1,%2,%3}, {%4,%5,%6,%7}, {%8,%9}, {%0,%1,%2,%3};"
        : "+r"(c[0]), "+r"(c[1]), "+r"(c[2]), "+r"(c[3])
        : "r"(a[0]), "r"(a[1]), "r"(a[2]), "r"(a[3]), "r"(b[0]), "r"(b[1]));
}

// ---------------------------------------------------------------------------
// Kernel 1 (fused prep): blocks [0,SEQ) do per-row activation quant,
// blocks [SEQ, SEQ+4096) convert W f32 -> int8. Overlaps both DRAM streams.
// ---------------------------------------------------------------------------
DINLINE int q1(float v, float s) {
    return (int)fminf(fmaxf(rintf(v * s), -128.f), 127.f);
}
DINLINE uint32_t qpack4(float4 v, float s) {
    uint32_t b0 = (uint32_t)q1(v.x, s) & 0xFF;
    uint32_t b1 = (uint32_t)q1(v.y, s) & 0xFF;
    uint32_t b2 = (uint32_t)q1(v.z, s) & 0xFF;
    uint32_t b3 = (uint32_t)q1(v.w, s) & 0xFF;
    return b0 | (b1 << 8) | (b2 << 16) | (b3 << 24);
}

__global__ void __launch_bounds__(256) prep_kernel(const float* __restrict__ x,
                                                   const float* __restrict__ W) {
    const int tid = threadIdx.x;
    if (blockIdx.x < SEQ) {
        const int row = blockIdx.x;
        const float4* xr = reinterpret_cast<const float4*>(x + (size_t)row * DIM);

        float4 v[4];
        float m = 0.f;
#pragma unroll
        for (int i = 0; i < 4; i++) {
            v[i] = xr[tid + i * 256];
            m = fmaxf(m, fmaxf(fmaxf(fabsf(v[i].x), fabsf(v[i].y)),
                               fmaxf(fabsf(v[i].z), fabsf(v[i].w))));
        }
        __shared__ float red[8];
#pragma unroll
        for (int o = 16; o > 0; o >>= 1) m = fmaxf(m, __shfl_xor_sync(~0u, m, o));
        if ((tid & 31) == 0) red[tid >> 5] = m;
        __syncthreads();
        if (tid < 8) {
            float t = red[tid];
#pragma unroll
            for (int o = 4; o > 0; o >>= 1) t = fmaxf(t, __shfl_xor_sync(0xff, t, o));
            if (tid == 0) {
                float scale = 127.0f / fmaxf(t, 1e-5f);
                red[0] = scale;
                g_rscale[row] = 1.0f / scale;
            }
        }
        __syncthreads();
        const float scale = red[0];

        uint32_t* qr = reinterpret_cast<uint32_t*>(g_qx + (size_t)row * DIM);
#pragma unroll
        for (int i = 0; i < 4; i++) qr[tid + i * 256] = qpack4(v[i], scale);
    } else {
        const int bid = blockIdx.x - SEQ;
        const float4* src = reinterpret_cast<const float4*>(W);
        uint32_t* dst = reinterpret_cast<uint32_t*>(g_wb);
#pragma unroll
        for (int i = 0; i < 4; i++) {
            size_t idx = (size_t)bid * 1024 + tid + i * 256;
            float4 v = src[idx];
            uint32_t b0 = (uint32_t)(int)v.x & 0xFF;
            uint32_t b1 = (uint32_t)(int)v.y & 0xFF;
            uint32_t b2 = (uint32_t)(int)v.z & 0xFF;
            uint32_t b3 = (uint32_t)(int)v.w & 0xFF;
            dst[idx] = b0 | (b1 << 8) | (b2 << 16) | (b3 << 24);
        }
    }
}

// ---------------------------------------------------------------------------
// Kernel 2: int8 IMMA GEMM  out[m,n] = (sum_k q*W) * rscale[m] + bias[n], * 1/ws
// CTA tile 128x128, 4 warps (warp tile 64x64), K-stage 64B, 4-stage cp.async,
// single barrier per K-iter.
// ---------------------------------------------------------------------------
constexpr int MT = 128;
constexpr int NT = 128;
constexpr int KSTG = 64;                      // int8 elems (= bytes) per K stage
constexpr int STAGES = 4;
constexpr int NKIT = DIM / KSTG;              // 64
constexpr int ASTRIDE = 80;                   // padded row stride (conflict-free ldmatrix)
constexpr uint32_t TILE_BYTES = 128 * ASTRIDE;        // 10240 per operand
constexpr uint32_t STAGE_BYTES = 2 * TILE_BYTES;      // 20480
constexpr uint32_t SM_TOTAL = STAGES * STAGE_BYTES;   // 81920

__global__ void __launch_bounds__(128, 2) gemm_kernel(const float* __restrict__ bias,
                                                      const float* __restrict__ wsp,
                                                      float* __restrict__ out) {
    extern __shared__ char smem[];
    const uint32_t sb = smem_u32(smem);
    const int tid = threadIdx.x;
    const int lane = tid & 31;
    const int warp = tid >> 5;
    const int warp_m = warp & 1;      // 2 warps along M  (2*64 = 128)
    const int warp_n = warp >> 1;     // 2 warps along N  (2*64 = 128)
    const int m0 = blockIdx.y * MT;
    const int n0 = blockIdx.x * NT;

    const char* const abase = reinterpret_cast<const char*>(g_qx) + (size_t)m0 * DIM;
    const char* const bbase = reinterpret_cast<const char*>(g_wb) + (size_t)n0 * DIM;

    // cp.async: per stage, 512 A-chunks + 512 B-chunks of 16B over 128 threads
    // chunk c in [0,512): row = c>>2, seg = c&3
    auto load_stage = [&](int kit) {
        const uint32_t sbb = sb + (uint32_t)(kit % STAGES) * STAGE_BYTES;
        const size_t kbyte = (size_t)kit * KSTG;
#pragma unroll
        for (int i = 0; i < 4; i++) {
            int c = tid + i * 128;
            int row = c >> 2, seg = c & 3;
            CP_ASYNC16(sbb + row * ASTRIDE + seg * 16,
                       abase + (size_t)row * DIM + kbyte + seg * 16);
        }
#pragma unroll
        for (int i = 0; i < 4; i++) {
            int c = tid + i * 128;
            int row = c >> 2, seg = c & 3;
            CP_ASYNC16(sbb + TILE_BYTES + row * ASTRIDE + seg * 16,
                       bbase + (size_t)row * DIM + kbyte + seg * 16);
        }
    };

    // ldmatrix lane addressing (stage-0 relative), identical fragment mapping
    // to the validated round-3 kernel.
    const int aRow = (lane & 7) + ((lane >> 3) & 1) * 8;
    const int aKoff = (lane >> 4) * 16;
    const uint32_t addrA0 = sb + (uint32_t)((warp_m * 64 + aRow) * ASTRIDE + aKoff);
    const int bRow = (lane & 7) + (lane >> 4) * 8;
    const int bKoff = ((lane >> 3) & 1) * 16;
    uint32_t addrB0[4];
#pragma unroll
    for (int j = 0; j < 4; j++)
        addrB0[j] = sb + TILE_BYTES +
                    (uint32_t)((warp_n * 64 + j * 16 + bRow) * ASTRIDE + bKoff);

    int acc[4][8][4];
#pragma unroll
    for (int tm = 0; tm < 4; tm++)
#pragma unroll
        for (int tn = 0; tn < 8; tn++)
#pragma unroll
            for (int r = 0; r < 4; r++) acc[tm][tn][r] = 0;

    // prologue: fill 3 stages
    load_stage(0); CP_COMMIT();
    load_stage(1); CP_COMMIT();
    load_stage(2); CP_COMMIT();

    for (int i = 0; i < NKIT; i++) {
        CP_WAIT2();               // own cp.asyncs for stage i complete
        __syncthreads();          // everyone's stage-i data visible; iter i-1 reads done

        if (i + 3 < NKIT) load_stage(i + 3);  // refill buffer (i-1)%4 (safe post-barrier)
        CP_COMMIT();

        const uint32_t so = (uint32_t)(i % STAGES) * STAGE_BYTES;
#pragma unroll
        for (int ks = 0; ks < 2; ks++) {
            const uint32_t ko = so + ks * 32;
            uint32_t af[4][4];
#pragma unroll
            for (int tm = 0; tm < 4; tm++)
                ldm_x4(af[tm], addrA0 + ko + tm * 16 * ASTRIDE);
            uint32_t bf[8][2];
#pragma unroll
            for (int j = 0; j < 4; j++) {
                uint32_t r[4];
                ldm_x4(r, addrB0[j] + ko);
                bf[2 * j][0] = r[0]; bf[2 * j][1] = r[1];
                bf[2 * j + 1][0] = r[2]; bf[2 * j + 1][1] = r[3];
            }
#pragma unroll
            for (int tm = 0; tm < 4; tm++)
#pragma unroll
                for (int tn = 0; tn < 8; tn++)
                    mma_s8(acc[tm][tn], af[tm], bf[tn]);
        }
    }

    // -------------------- epilogue --------------------
    const float inv_ws = 1.0f / wsp[0];
#pragma unroll
    for (int tm = 0; tm < 4; tm++) {
        const int r0 = m0 + warp_m * 64 + tm * 16 + (lane >> 2);
        const int r1 = r0 + 8;
        const float rs0 = g_rscale[r0];
        const float rs1 = g_rscale[r1];
        float* o0 = out + (size_t)r0 * OUT;
        float* o1 = out + (size_t)r1 * OUT;
#pragma unroll
        for (int tn = 0; tn < 8; tn++) {
            const int col = n0 + warp_n * 64 + tn * 8 + (lane & 3) * 2;
            const float b0v = bias[col], b1v = bias[col + 1];
            float2 v0, v1;
            v0.x = ((float)acc[tm][tn][0] * rs0 + b0v) * inv_ws;
            v0.y = ((float)acc[tm][tn][1] * rs0 + b1v) * inv_ws;
            v1.x = ((float)acc[tm][tn][2] * rs1 + b0v) * inv_ws;
            v1.y = ((float)acc[tm][tn][3] * rs1 + b1v) * inv_ws;
            *reinterpret_cast<float2*>(o0 + col) = v0;
            *reinterpret_cast<float2*>(o1 + col) = v1;
        }
    }
}

// ---------------------------------------------------------------------------
// Launch
// ---------------------------------------------------------------------------
extern "C" void kernel_launch(void* const* d_in, const int* in_sizes, int n_in,
                              void* d_out, int out_size) {
    (void)in_sizes; (void)n_in; (void)out_size;
    const float* x    = (const float*)d_in[0];
    const float* W    = (const float*)d_in[1];
    const float* bias = (const float*)d_in[2];
    const float* ws   = (const float*)d_in[3];
    float* out = (float*)d_out;

    prep_kernel<<<SEQ + (int)(((size_t)OUT * DIM / 4) / 1024), 256>>>(x, W);

    cudaFuncSetAttribute(gemm_kernel, cudaFuncAttributeMaxDynamicSharedMemorySize, SM_TOTAL);
    gemm_kernel<<<dim3(OUT / NT, SEQ / MT), 128, SM_TOTAL>>>(bias, ws, out);
}